// round 5
// baseline (speedup 1.0000x reference)
#include <cuda_runtime.h>
#include <cstdint>

#define N_BATCH 8
#define K_ANCH  9
#define Hdim    120
#define Wdim    120
#define HW      (Hdim*Wdim)
#define TOT     (HW*K_ANCH)       /* 129600 */
#define PRE     3000
#define POST    300
#define CAND_MAX 8192
#define NBUCKET  4096
#define NT       256              /* scan block size */
#define SLOTS    12               /* 256*12 = 3072 >= 3000 */
#define NWARP    (NT/32)

// ---------------- scratch (static device globals; no allocation) ------------
__device__ int    g_topk_idx[N_BATCH*PRE];
__device__ float  g_topk_score[N_BATCH*PRE];
__device__ float4 g_boxes[N_BATCH*PRE];
__device__ float  g_selscore[N_BATCH*POST];

// monotone float->uint key (descending floats -> descending uints)
__device__ __forceinline__ unsigned int fkey(float x) {
    unsigned int u = __float_as_uint(x);
    return (u & 0x80000000u) ? ~u : (u | 0x80000000u);
}
__device__ __forceinline__ float fkey_inv(unsigned int k) {
    return (k & 0x80000000u) ? __uint_as_float(k ^ 0x80000000u)
                             : __uint_as_float(~k);
}
__device__ __forceinline__ float boxarea(float4 b) {
    return __fmul_rn(__fadd_rn(__fsub_rn(b.z, b.x), 1.0f),
                     __fadd_rn(__fsub_rn(b.w, b.y), 1.0f));
}

// ---------------- Stage 1: per-batch exact top-3000 -------------------------
extern "C" __global__ void __launch_bounds__(1024)
topk_kernel(const float* __restrict__ cls) {
    extern __shared__ unsigned long long s_cand[];   // 8192 * 8B = 64KB
    __shared__ unsigned int hist[NBUCKET];           // 16KB
    __shared__ unsigned int psum[1024];              // 4KB
    __shared__ unsigned int s_B;
    __shared__ unsigned int s_cnt;

    const int n   = blockIdx.x;
    const int tid = threadIdx.x;
    const float* sc = cls + (size_t)n * TOT;

    for (int b = tid; b < NBUCKET; b += 1024) hist[b] = 0;
    if (tid == 0) s_cnt = 0;
    __syncthreads();

    for (int i = tid; i < TOT; i += 1024)
        atomicAdd(&hist[fkey(sc[i]) >> 20], 1u);
    __syncthreads();

    psum[tid] = hist[4*tid] + hist[4*tid+1] + hist[4*tid+2] + hist[4*tid+3];
    __syncthreads();

    if (tid == 0) {
        unsigned int acc = 0;
        int S = 0;
        for (int s = 31; s >= 0; --s) {
            unsigned int q = 0;
            for (int t = 0; t < 32; ++t) q += psum[s*32 + t];
            if (acc + q >= PRE) { S = s; break; }
            acc += q;
        }
        int Pb = S*32;
        for (int t = 31; t >= 0; --t) {
            unsigned int q = psum[S*32 + t];
            if (acc + q >= PRE) { Pb = S*32 + t; break; }
            acc += q;
        }
        unsigned int B = (unsigned int)(Pb*4);
        for (int b = 3; b >= 0; --b) {
            unsigned int q = hist[Pb*4 + b];
            if (acc + q >= PRE) { B = (unsigned int)(Pb*4 + b); break; }
            acc += q;
        }
        s_B = B;
    }
    __syncthreads();

    const unsigned int thr = s_B << 20;
    for (int i = tid; i < TOT; i += 1024) {
        unsigned int k = fkey(sc[i]);
        if (k >= thr) {
            unsigned int pos = atomicAdd(&s_cnt, 1u);
            if (pos < CAND_MAX)
                s_cand[pos] = ((unsigned long long)k << 32) |
                              (unsigned int)(~(unsigned int)i);
        }
    }
    __syncthreads();

    const unsigned int cnt = s_cnt;               // guaranteed >= PRE
    const int S_sort = (cnt <= 4096u) ? 4096 : 8192;
    for (int i = (int)cnt + tid; i < S_sort; i += 1024) s_cand[i] = 0ull;
    __syncthreads();

    // bitonic sort, descending on u64 (ties: smaller idx first via ~idx)
    for (int k = 2; k <= S_sort; k <<= 1) {
        for (int j = k >> 1; j > 0; j >>= 1) {
            for (int i = tid; i < S_sort; i += 1024) {
                int ixj = i ^ j;
                if (ixj > i) {
                    unsigned long long a = s_cand[i], b = s_cand[ixj];
                    bool dir = (i & k) != 0;
                    if ((a < b) != dir) { s_cand[i] = b; s_cand[ixj] = a; }
                }
            }
            __syncthreads();
        }
    }

    for (int r = tid; r < PRE; r += 1024) {
        unsigned long long c = s_cand[r];
        unsigned int key = (unsigned int)(c >> 32);
        int idx = (int)(~(unsigned int)(c & 0xFFFFFFFFull));
        g_topk_idx[n*PRE + r]   = idx;
        g_topk_score[n*PRE + r] = fkey_inv(key);
    }
}

// ---------------- Stage 2: gather-compute selected boxes --------------------
extern "C" __global__ void boxes_kernel(const float* __restrict__ deltas) {
    int g = blockIdx.x*blockDim.x + threadIdx.x;
    if (g >= N_BATCH*PRE) return;
    const int n = g / PRE;
    const int o = g_topk_idx[g];

    const int kk = o % K_ANCH;
    const int t0 = o / K_ANCH;
    const int ww = t0 % Wdim;
    const int hh = t0 / Wdim;

    const float ratios_[3] = {0.5f, 1.0f, 2.0f};
    const float scales_[3] = {8.0f, 16.0f, 32.0f};

    float v[4];
#pragma unroll
    for (int jj = 0; jj < 4; ++jj) {
        int f  = ((kk*4 + jj)*Hdim + hh)*Wdim + ww;
        int j  = f & 3;
        int r1 = f >> 2;
        int k  = r1 % K_ANCH;
        int r2 = r1 / K_ANCH;
        int w  = r2 % Wdim;
        int h  = r2 / Wdim;

        float sr  = __fsqrt_rn(ratios_[k/3]);
        float wsz = __fdiv_rn(__fmul_rn(16.0f, scales_[k%3]), sr);
        float hsz = __fmul_rn(__fmul_rn(16.0f, scales_[k%3]), sr);
        float cx  = __fmul_rn(__fadd_rn((float)w, 0.5f), 16.0f);
        float cy  = __fmul_rn(__fadd_rn((float)h, 0.5f), 16.0f);

        float a;
        if      (j == 0) a = __fsub_rn(cx, __fmul_rn(0.5f, wsz));
        else if (j == 1) a = __fsub_rn(cy, __fmul_rn(0.5f, hsz));
        else if (j == 2) a = __fadd_rn(cx, __fmul_rn(0.5f, wsz));
        else             a = __fadd_rn(cy, __fmul_rn(0.5f, hsz));

        float d   = deltas[((size_t)n*36 + (k*4 + j))*HW + h*Wdim + w];
        float val = __fadd_rn(a, d);
        v[jj] = fminf(fmaxf(val, 0.0f), 1919.0f);
    }
    g_boxes[g] = make_float4(v[0], v[1], v[2], v[3]);
}

// ---------------- Stage 3+4 fused: register-resident dynamic NMS ------------
// 256 threads/batch, 12 boxes/thread in REGISTERS (all accesses compile-time
// indexed; alive flags are a bitmask). One barrier per kept box:
//   IoU+kill -> warp REDUX.MIN -> warp owner posts (idx,box) to ping-pong
//   per-warp smem slot -> barrier -> all threads min over 8 slots, fetch box.
extern "C" __global__ void __launch_bounds__(NT)
scan_kernel(float* __restrict__ out) {
    const int n = blockIdx.x;
    const int tid  = threadIdx.x;
    const int lane = tid & 31;
    const int wid  = tid >> 5;
    __shared__ float4 s_bslot[2][NWARP];
    __shared__ float  s_aslot[2][NWARP];
    __shared__ int    s_wmin[2][NWARP];
    __shared__ int    s_kept[POST];

    float4 bx[SLOTS];
    float  ar[SLOTS];
    unsigned aliveM = 0u;
#pragma unroll
    for (int s = 0; s < SLOTS; ++s) {
        int i = tid + s*NT;
        if (i < PRE) {
            float4 b = g_boxes[n*PRE + i];
            bx[s] = b;
            ar[s] = boxarea(b);
            aliveM |= (1u << s);
        } else {
            bx[s] = make_float4(0,0,0,0);
            ar[s] = 0.0f;
        }
    }

    // first kept box is always index 0
    float4 kb = g_boxes[n*PRE];          // uniform broadcast load
    float  ka = boxarea(kb);
    if (tid == 0) aliveM &= ~1u;
    int i_cur = 0;
    int nk = 0;
    const int INF = 0x7fffffff;

    while (true) {
        if (tid == 0) s_kept[nk] = i_cur;
        ++nk;
        if (nk >= POST) break;
        const int p = nk & 1;

        int local_next = INF;
#pragma unroll
        for (int s = 0; s < SLOTS; ++s) {
            if (aliveM & (1u << s)) {
                float xx1 = fmaxf(kb.x, bx[s].x), yy1 = fmaxf(kb.y, bx[s].y);
                float xx2 = fminf(kb.z, bx[s].z), yy2 = fminf(kb.w, bx[s].w);
                float iw = fmaxf(__fadd_rn(__fsub_rn(xx2, xx1), 1.0f), 0.0f);
                float ih = fmaxf(__fadd_rn(__fsub_rn(yy2, yy1), 1.0f), 0.0f);
                float inter = __fmul_rn(iw, ih);
                float denom = __fsub_rn(__fadd_rn(ka, ar[s]), inter);
                if (__fdiv_rn(inter, denom) > 0.5f)
                    aliveM &= ~(1u << s);
                else
                    local_next = min(local_next, tid + s*NT);
            }
        }
        int wmin = __reduce_min_sync(0xffffffffu, local_next);
        if (lane == 0) s_wmin[p][wid] = wmin;
        if (local_next == wmin && wmin != INF) {
            // exactly one thread per warp (indices are uniquely owned)
#pragma unroll
            for (int s = 0; s < SLOTS; ++s) {
                if (tid + s*NT == wmin) {
                    s_bslot[p][wid] = bx[s];
                    s_aslot[p][wid] = ar[s];
                }
            }
        }
        __syncthreads();

        int imin = INF, wwin = 0;
#pragma unroll
        for (int w = 0; w < NWARP; ++w) {
            int v = s_wmin[p][w];
            if (v < imin) { imin = v; wwin = w; }
        }
        if (imin == INF) break;
        i_cur = imin;
        kb = s_bslot[p][wwin];           // dynamic smem index: fine (LDS)
        ka = s_aslot[p][wwin];
        if ((i_cur & (NT-1)) == tid)     // owner consumes its box
            aliveM &= ~(1u << (i_cur >> 8));
    }
    __syncthreads();

    for (int r = tid; r < POST; r += NT) {
        float sc = 0.0f, x1 = 0.0f, y1 = 0.0f, x2 = 0.0f, y2 = 0.0f;
        if (r < nk) {
            int i = s_kept[r];
            float4 b = g_boxes[n*PRE + i];
            x1 = b.x; y1 = b.y; x2 = b.z; y2 = b.w;
            sc = g_topk_score[n*PRE + i];
        }
        float* o = out + (size_t)(n*POST + r)*5;
        o[1] = x1; o[2] = y1; o[3] = x2; o[4] = y2;
        g_selscore[n*POST + r] = sc;
    }
}

// ---------------- Stage 5: score column = batch 7's selected scores ---------
extern "C" __global__ void final_kernel(float* __restrict__ out) {
    int g = blockIdx.x*blockDim.x + threadIdx.x;
    if (g >= N_BATCH*POST) return;
    int r = g % POST;
    out[(size_t)g*5] = g_selscore[7*POST + r];
}

// ---------------- launch -----------------------------------------------------
extern "C" void kernel_launch(void* const* d_in, const int* in_sizes, int n_in,
                              void* d_out, int out_size) {
    const float* cls;
    const float* deltas;
    if (in_sizes[0] == N_BATCH*K_ANCH*HW) {     // 1,036,800
        cls = (const float*)d_in[0]; deltas = (const float*)d_in[1];
    } else {
        cls = (const float*)d_in[1]; deltas = (const float*)d_in[0];
    }
    float* out = (float*)d_out;

    cudaFuncSetAttribute(topk_kernel,
                         cudaFuncAttributeMaxDynamicSharedMemorySize, 65536);

    topk_kernel<<<N_BATCH, 1024, 65536>>>(cls);
    boxes_kernel<<<(N_BATCH*PRE + 255)/256, 256>>>(deltas);
    scan_kernel<<<N_BATCH, NT>>>(out);
    final_kernel<<<(N_BATCH*POST + 255)/256, 256>>>(out);
}

// round 6
// speedup vs baseline: 3.0238x; 3.0238x over previous
#include <cuda_runtime.h>
#include <cstdint>

#define N_BATCH 8
#define K_ANCH  9
#define Hdim    120
#define Wdim    120
#define HW      (Hdim*Wdim)
#define TOT     (HW*K_ANCH)       /* 129600 */
#define PRE     3000
#define POST    300
#define NWORDS  47                /* ceil(3000/64) */
#define MPITCH  48
#define CAND_MAX 8192
#define NBUCKET  4096

// ---------------- scratch (static device globals; no allocation) ------------
__device__ int    g_topk_idx[N_BATCH*PRE];
__device__ float  g_topk_score[N_BATCH*PRE];
__device__ float4 g_boxes[N_BATCH*PRE];
__device__ unsigned long long g_mask[(size_t)N_BATCH*PRE*MPITCH];   // ~9.2MB
__device__ float  g_selscore[N_BATCH*POST];

// monotone float->uint key (descending floats -> descending uints)
__device__ __forceinline__ unsigned int fkey(float x) {
    unsigned int u = __float_as_uint(x);
    return (u & 0x80000000u) ? ~u : (u | 0x80000000u);
}
__device__ __forceinline__ float fkey_inv(unsigned int k) {
    return (k & 0x80000000u) ? __uint_as_float(k ^ 0x80000000u)
                             : __uint_as_float(~k);
}

// ---------------- Stage 1: per-batch exact top-3000 -------------------------
extern "C" __global__ void __launch_bounds__(1024)
topk_kernel(const float* __restrict__ cls) {
    extern __shared__ unsigned long long s_cand[];   // 8192 * 8B = 64KB
    __shared__ unsigned int hist[NBUCKET];           // 16KB
    __shared__ unsigned int psum[1024];              // 4KB
    __shared__ unsigned int s_B;
    __shared__ unsigned int s_cnt;

    const int n   = blockIdx.x;
    const int tid = threadIdx.x;
    const float* sc = cls + (size_t)n * TOT;

    for (int b = tid; b < NBUCKET; b += 1024) hist[b] = 0;
    if (tid == 0) s_cnt = 0;
    __syncthreads();

    for (int i = tid; i < TOT; i += 1024)
        atomicAdd(&hist[fkey(sc[i]) >> 20], 1u);
    __syncthreads();

    psum[tid] = hist[4*tid] + hist[4*tid+1] + hist[4*tid+2] + hist[4*tid+3];
    __syncthreads();

    if (tid == 0) {
        unsigned int acc = 0;
        int S = 0;
        for (int s = 31; s >= 0; --s) {
            unsigned int q = 0;
            for (int t = 0; t < 32; ++t) q += psum[s*32 + t];
            if (acc + q >= PRE) { S = s; break; }
            acc += q;
        }
        int Pb = S*32;
        for (int t = 31; t >= 0; --t) {
            unsigned int q = psum[S*32 + t];
            if (acc + q >= PRE) { Pb = S*32 + t; break; }
            acc += q;
        }
        unsigned int B = (unsigned int)(Pb*4);
        for (int b = 3; b >= 0; --b) {
            unsigned int q = hist[Pb*4 + b];
            if (acc + q >= PRE) { B = (unsigned int)(Pb*4 + b); break; }
            acc += q;
        }
        s_B = B;
    }
    __syncthreads();

    const unsigned int thr = s_B << 20;
    for (int i = tid; i < TOT; i += 1024) {
        unsigned int k = fkey(sc[i]);
        if (k >= thr) {
            unsigned int pos = atomicAdd(&s_cnt, 1u);
            if (pos < CAND_MAX)
                s_cand[pos] = ((unsigned long long)k << 32) |
                              (unsigned int)(~(unsigned int)i);
        }
    }
    __syncthreads();

    const unsigned int cnt = s_cnt;               // guaranteed >= PRE
    const int S_sort = (cnt <= 4096u) ? 4096 : 8192;
    for (int i = (int)cnt + tid; i < S_sort; i += 1024) s_cand[i] = 0ull;
    __syncthreads();

    // bitonic sort, descending on u64 (ties: smaller idx first via ~idx)
    for (int k = 2; k <= S_sort; k <<= 1) {
        for (int j = k >> 1; j > 0; j >>= 1) {
            for (int i = tid; i < S_sort; i += 1024) {
                int ixj = i ^ j;
                if (ixj > i) {
                    unsigned long long a = s_cand[i], b = s_cand[ixj];
                    bool dir = (i & k) != 0;
                    if ((a < b) != dir) { s_cand[i] = b; s_cand[ixj] = a; }
                }
            }
            __syncthreads();
        }
    }

    for (int r = tid; r < PRE; r += 1024) {
        unsigned long long c = s_cand[r];
        unsigned int key = (unsigned int)(c >> 32);
        int idx = (int)(~(unsigned int)(c & 0xFFFFFFFFull));
        g_topk_idx[n*PRE + r]   = idx;
        g_topk_score[n*PRE + r] = fkey_inv(key);
    }
}

// ---------------- Stage 2: gather-compute selected boxes --------------------
extern "C" __global__ void boxes_kernel(const float* __restrict__ deltas) {
    int g = blockIdx.x*blockDim.x + threadIdx.x;
    if (g >= N_BATCH*PRE) return;
    const int n = g / PRE;
    const int o = g_topk_idx[g];

    const int kk = o % K_ANCH;
    const int t0 = o / K_ANCH;
    const int ww = t0 % Wdim;
    const int hh = t0 / Wdim;

    const float ratios_[3] = {0.5f, 1.0f, 2.0f};
    const float scales_[3] = {8.0f, 16.0f, 32.0f};

    float v[4];
#pragma unroll
    for (int jj = 0; jj < 4; ++jj) {
        int f  = ((kk*4 + jj)*Hdim + hh)*Wdim + ww;
        int j  = f & 3;
        int r1 = f >> 2;
        int k  = r1 % K_ANCH;
        int r2 = r1 / K_ANCH;
        int w  = r2 % Wdim;
        int h  = r2 / Wdim;

        float sr  = __fsqrt_rn(ratios_[k/3]);
        float wsz = __fdiv_rn(__fmul_rn(16.0f, scales_[k%3]), sr);
        float hsz = __fmul_rn(__fmul_rn(16.0f, scales_[k%3]), sr);
        float cx  = __fmul_rn(__fadd_rn((float)w, 0.5f), 16.0f);
        float cy  = __fmul_rn(__fadd_rn((float)h, 0.5f), 16.0f);

        float a;
        if      (j == 0) a = __fsub_rn(cx, __fmul_rn(0.5f, wsz));
        else if (j == 1) a = __fsub_rn(cy, __fmul_rn(0.5f, hsz));
        else if (j == 2) a = __fadd_rn(cx, __fmul_rn(0.5f, wsz));
        else             a = __fadd_rn(cy, __fmul_rn(0.5f, hsz));

        float d   = deltas[((size_t)n*36 + (k*4 + j))*HW + h*Wdim + w];
        float val = __fadd_rn(a, d);
        v[jj] = fminf(fmaxf(val, 0.0f), 1919.0f);
    }
    g_boxes[g] = make_float4(v[0], v[1], v[2], v[3]);
}

// ---------------- Stage 3: NMS suppression bitmask (fdiv, R1-proven) --------
extern "C" __global__ void mask_kernel() {
    const int rb = blockIdx.x, cb = blockIdx.y, n = blockIdx.z;
    if (cb < rb) return;
    __shared__ float4 colbox[64];
    __shared__ float  colarea[64];
    const int tid = threadIdx.x;
    const int cj = cb*64 + tid;
    float4 cbx = (cj < PRE) ? g_boxes[n*PRE + cj] : make_float4(0,0,0,0);
    colbox[tid] = cbx;
    colarea[tid] = __fmul_rn(__fadd_rn(__fsub_rn(cbx.z, cbx.x), 1.0f),
                             __fadd_rn(__fsub_rn(cbx.w, cbx.y), 1.0f));
    __syncthreads();

    const int i = rb*64 + tid;
    if (i >= PRE) return;
    const float4 bi = g_boxes[n*PRE + i];
    const float ai = __fmul_rn(__fadd_rn(__fsub_rn(bi.z, bi.x), 1.0f),
                               __fadd_rn(__fsub_rn(bi.w, bi.y), 1.0f));
    unsigned long long bits = 0ull;
    const int jmax = min(64, PRE - cb*64);
    for (int c = 0; c < jmax; ++c) {
        int j = cb*64 + c;
        if (j <= i) continue;
        float4 bj = colbox[c];
        float aj = colarea[c];
        float xx1 = fmaxf(bi.x, bj.x), yy1 = fmaxf(bi.y, bj.y);
        float xx2 = fminf(bi.z, bj.z), yy2 = fminf(bi.w, bj.w);
        float iw = fmaxf(__fadd_rn(__fsub_rn(xx2, xx1), 1.0f), 0.0f);
        float ih = fmaxf(__fadd_rn(__fsub_rn(yy2, yy1), 1.0f), 0.0f);
        float inter = __fmul_rn(iw, ih);
        float denom = __fsub_rn(__fadd_rn(ai, aj), inter);
        float iou   = __fdiv_rn(inter, denom);
        if (iou > 0.5f) bits |= (1ull << c);
    }
    g_mask[((size_t)n*PRE + i)*MPITCH + cb] = bits;
}

// ---------------- Stage 4: word-blocked mask scan ----------------------------
// One warp per batch. Survivor bitset rem distributed over lanes (word lane
// in rem0, word 32+lane in rem1). Words resolved 64 bits at a time using the
// prefetched 64x64 diagonal mask block in smem (serial part = smem/ALU only);
// the kept rows of the word are applied to future words as one batch of
// independent L2 loads (OR-accumulated).
extern "C" __global__ void __launch_bounds__(32)
scan_kernel(float* __restrict__ out) {
    const int n = blockIdx.x;
    const int lane = threadIdx.x;
    __shared__ unsigned long long s_diag[2][64];
    __shared__ int s_kept[POST];
    const unsigned FULL = 0xffffffffu;

    unsigned long long rem0 = ~0ull;                       // words 0..31
    unsigned long long rem1 =
        (lane < 14) ? ~0ull :
        (lane == 14 ? ((1ull << 56) - 1ull) : 0ull);       // words 32..46

    const unsigned long long* __restrict__ mbase =
        g_mask + (size_t)n * PRE * MPITCH;

    // preload diagonal block of word 0 (rows 0..63, word 0)
    s_diag[0][lane]      = mbase[(size_t)lane * MPITCH];
    s_diag[0][32 + lane] = mbase[(size_t)(32 + lane) * MPITCH];
    __syncwarp();

    int nk = 0;
    for (int w = 0; w < NWORDS && nk < POST; ++w) {
        // uniform fetch of rem word w
        unsigned long long cur = (w < 32)
            ? __shfl_sync(FULL, rem0, w)
            : __shfl_sync(FULL, rem1, w - 32);

        // prefetch diagonal block of word w+1 (overlaps with serial resolve)
        const int pb = (w + 1) & 1, cb = w & 1;
        if (w + 1 < NWORDS) {
            int base = (w + 1) * 64;
            int r0 = base + lane, r1 = base + 32 + lane;
            s_diag[pb][lane]      = (r0 < PRE)
                ? mbase[(size_t)r0 * MPITCH + (w + 1)] : 0ull;
            s_diag[pb][32 + lane] = (r1 < PRE)
                ? mbase[(size_t)r1 * MPITCH + (w + 1)] : 0ull;
        }

        // serial intra-word greedy resolve (uniform on all lanes; smem only)
        unsigned long long keptbits = 0ull;
        while (cur && nk < POST) {
            int b = __ffsll((long long)cur) - 1;
            keptbits |= (1ull << b);
            s_kept[nk] = w * 64 + b;     // all lanes store identical value
            ++nk;
            cur &= ~(1ull << b);
            cur &= ~s_diag[cb][b];
        }

        // batch-apply all kept rows of this word to future words
        unsigned long long or0 = 0ull, or1 = 0ull;
        unsigned long long kb = keptbits;
        while (kb) {
            int b = __ffsll((long long)kb) - 1;
            kb &= kb - 1ull;
            const unsigned long long* row =
                mbase + (size_t)(w * 64 + b) * MPITCH;
            or0 |= row[lane];
            or1 |= (lane < 15) ? row[32 + lane] : 0ull;
        }
        rem0 &= ~or0;
        rem1 &= ~or1;
        // retire processed word
        if (w < 32) { if (lane == w)      rem0 = 0ull; }
        else        { if (lane == w - 32) rem1 = 0ull; }
        __syncwarp();
    }
    __syncwarp();

    for (int r = lane; r < POST; r += 32) {
        float sc = 0.0f, x1 = 0.0f, y1 = 0.0f, x2 = 0.0f, y2 = 0.0f;
        if (r < nk) {
            int i = s_kept[r];
            float4 b = g_boxes[n*PRE + i];
            x1 = b.x; y1 = b.y; x2 = b.z; y2 = b.w;
            sc = g_topk_score[n*PRE + i];
        }
        float* o = out + (size_t)(n*POST + r)*5;
        o[1] = x1; o[2] = y1; o[3] = x2; o[4] = y2;
        g_selscore[n*POST + r] = sc;
    }
}

// ---------------- Stage 5: score column = batch 7's selected scores ---------
extern "C" __global__ void final_kernel(float* __restrict__ out) {
    int g = blockIdx.x*blockDim.x + threadIdx.x;
    if (g >= N_BATCH*POST) return;
    int r = g % POST;
    out[(size_t)g*5] = g_selscore[7*POST + r];
}

// ---------------- launch -----------------------------------------------------
extern "C" void kernel_launch(void* const* d_in, const int* in_sizes, int n_in,
                              void* d_out, int out_size) {
    const float* cls;
    const float* deltas;
    if (in_sizes[0] == N_BATCH*K_ANCH*HW) {     // 1,036,800
        cls = (const float*)d_in[0]; deltas = (const float*)d_in[1];
    } else {
        cls = (const float*)d_in[1]; deltas = (const float*)d_in[0];
    }
    float* out = (float*)d_out;

    cudaFuncSetAttribute(topk_kernel,
                         cudaFuncAttributeMaxDynamicSharedMemorySize, 65536);

    topk_kernel<<<N_BATCH, 1024, 65536>>>(cls);
    boxes_kernel<<<(N_BATCH*PRE + 255)/256, 256>>>(deltas);
    dim3 mg(NWORDS, NWORDS, N_BATCH);
    mask_kernel<<<mg, 64>>>();
    scan_kernel<<<N_BATCH, 32>>>(out);
    final_kernel<<<(N_BATCH*POST + 255)/256, 256>>>(out);
}

// round 7
// speedup vs baseline: 4.2700x; 1.4121x over previous
#include <cuda_runtime.h>
#include <cstdint>

#define N_BATCH 8
#define K_ANCH  9
#define Hdim    120
#define Wdim    120
#define HW      (Hdim*Wdim)
#define TOT     (HW*K_ANCH)       /* 129600 */
#define PRE     3000
#define POST    300
#define NWORDS  47                /* ceil(3000/64) */
#define MPITCH  48
#define CAND_MAX 8192
#define NBUCKET  4096

// ---------------- scratch (static device globals; no allocation) ------------
__device__ int    g_topk_idx[N_BATCH*PRE];
__device__ float  g_topk_score[N_BATCH*PRE];
__device__ float4 g_boxes[N_BATCH*PRE];
__device__ unsigned long long g_mask[(size_t)N_BATCH*PRE*MPITCH];   // ~9.2MB
__device__ float  g_selscore[N_BATCH*POST];

// monotone float->uint key (descending floats -> descending uints)
__device__ __forceinline__ unsigned int fkey(float x) {
    unsigned int u = __float_as_uint(x);
    return (u & 0x80000000u) ? ~u : (u | 0x80000000u);
}
__device__ __forceinline__ float fkey_inv(unsigned int k) {
    return (k & 0x80000000u) ? __uint_as_float(k ^ 0x80000000u)
                             : __uint_as_float(~k);
}

// ---------------- Stage 1: per-batch exact top-3000 -------------------------
extern "C" __global__ void __launch_bounds__(1024)
topk_kernel(const float* __restrict__ cls) {
    extern __shared__ unsigned long long s_cand[];   // 8192 * 8B = 64KB
    __shared__ unsigned int hist[NBUCKET];           // 16KB
    __shared__ unsigned int psum[1024];              // 4KB
    __shared__ unsigned int s_B;
    __shared__ unsigned int s_cnt;

    const int n   = blockIdx.x;
    const int tid = threadIdx.x;
    const float* sc = cls + (size_t)n * TOT;

    for (int b = tid; b < NBUCKET; b += 1024) hist[b] = 0;
    if (tid == 0) s_cnt = 0;
    __syncthreads();

    for (int i = tid; i < TOT; i += 1024)
        atomicAdd(&hist[fkey(sc[i]) >> 20], 1u);
    __syncthreads();

    psum[tid] = hist[4*tid] + hist[4*tid+1] + hist[4*tid+2] + hist[4*tid+3];
    __syncthreads();

    if (tid == 0) {
        unsigned int acc = 0;
        int S = 0;
        for (int s = 31; s >= 0; --s) {
            unsigned int q = 0;
            for (int t = 0; t < 32; ++t) q += psum[s*32 + t];
            if (acc + q >= PRE) { S = s; break; }
            acc += q;
        }
        int Pb = S*32;
        for (int t = 31; t >= 0; --t) {
            unsigned int q = psum[S*32 + t];
            if (acc + q >= PRE) { Pb = S*32 + t; break; }
            acc += q;
        }
        unsigned int B = (unsigned int)(Pb*4);
        for (int b = 3; b >= 0; --b) {
            unsigned int q = hist[Pb*4 + b];
            if (acc + q >= PRE) { B = (unsigned int)(Pb*4 + b); break; }
            acc += q;
        }
        s_B = B;
    }
    __syncthreads();

    const unsigned int thr = s_B << 20;
    for (int i = tid; i < TOT; i += 1024) {
        unsigned int k = fkey(sc[i]);
        if (k >= thr) {
            unsigned int pos = atomicAdd(&s_cnt, 1u);
            if (pos < CAND_MAX)
                s_cand[pos] = ((unsigned long long)k << 32) |
                              (unsigned int)(~(unsigned int)i);
        }
    }
    __syncthreads();

    const unsigned int cnt = s_cnt;               // guaranteed >= PRE
    const int S_sort = (cnt <= 4096u) ? 4096 : 8192;
    for (int i = (int)cnt + tid; i < S_sort; i += 1024) s_cand[i] = 0ull;
    __syncthreads();

    // bitonic sort, descending on u64 (ties: smaller idx first via ~idx)
    for (int k = 2; k <= S_sort; k <<= 1) {
        for (int j = k >> 1; j > 0; j >>= 1) {
            for (int i = tid; i < S_sort; i += 1024) {
                int ixj = i ^ j;
                if (ixj > i) {
                    unsigned long long a = s_cand[i], b = s_cand[ixj];
                    bool dir = (i & k) != 0;
                    if ((a < b) != dir) { s_cand[i] = b; s_cand[ixj] = a; }
                }
            }
            __syncthreads();
        }
    }

    for (int r = tid; r < PRE; r += 1024) {
        unsigned long long c = s_cand[r];
        unsigned int key = (unsigned int)(c >> 32);
        int idx = (int)(~(unsigned int)(c & 0xFFFFFFFFull));
        g_topk_idx[n*PRE + r]   = idx;
        g_topk_score[n*PRE + r] = fkey_inv(key);
    }
}

// ---------------- Stage 2: gather-compute selected boxes --------------------
extern "C" __global__ void boxes_kernel(const float* __restrict__ deltas) {
    int g = blockIdx.x*blockDim.x + threadIdx.x;
    if (g >= N_BATCH*PRE) return;
    const int n = g / PRE;
    const int o = g_topk_idx[g];

    const int kk = o % K_ANCH;
    const int t0 = o / K_ANCH;
    const int ww = t0 % Wdim;
    const int hh = t0 / Wdim;

    const float ratios_[3] = {0.5f, 1.0f, 2.0f};
    const float scales_[3] = {8.0f, 16.0f, 32.0f};

    float v[4];
#pragma unroll
    for (int jj = 0; jj < 4; ++jj) {
        int f  = ((kk*4 + jj)*Hdim + hh)*Wdim + ww;
        int j  = f & 3;
        int r1 = f >> 2;
        int k  = r1 % K_ANCH;
        int r2 = r1 / K_ANCH;
        int w  = r2 % Wdim;
        int h  = r2 / Wdim;

        float sr  = __fsqrt_rn(ratios_[k/3]);
        float wsz = __fdiv_rn(__fmul_rn(16.0f, scales_[k%3]), sr);
        float hsz = __fmul_rn(__fmul_rn(16.0f, scales_[k%3]), sr);
        float cx  = __fmul_rn(__fadd_rn((float)w, 0.5f), 16.0f);
        float cy  = __fmul_rn(__fadd_rn((float)h, 0.5f), 16.0f);

        float a;
        if      (j == 0) a = __fsub_rn(cx, __fmul_rn(0.5f, wsz));
        else if (j == 1) a = __fsub_rn(cy, __fmul_rn(0.5f, hsz));
        else if (j == 2) a = __fadd_rn(cx, __fmul_rn(0.5f, wsz));
        else             a = __fadd_rn(cy, __fmul_rn(0.5f, hsz));

        float d   = deltas[((size_t)n*36 + (k*4 + j))*HW + h*Wdim + w];
        float val = __fadd_rn(a, d);
        v[jj] = fminf(fmaxf(val, 0.0f), 1919.0f);
    }
    g_boxes[g] = make_float4(v[0], v[1], v[2], v[3]);
}

// ---------------- Stage 3: NMS suppression bitmask (fdiv, R1-proven) --------
extern "C" __global__ void mask_kernel() {
    const int rb = blockIdx.x, cb = blockIdx.y, n = blockIdx.z;
    if (cb < rb) return;
    __shared__ float4 colbox[64];
    __shared__ float  colarea[64];
    const int tid = threadIdx.x;
    const int cj = cb*64 + tid;
    float4 cbx = (cj < PRE) ? g_boxes[n*PRE + cj] : make_float4(0,0,0,0);
    colbox[tid] = cbx;
    colarea[tid] = __fmul_rn(__fadd_rn(__fsub_rn(cbx.z, cbx.x), 1.0f),
                             __fadd_rn(__fsub_rn(cbx.w, cbx.y), 1.0f));
    __syncthreads();

    const int i = rb*64 + tid;
    if (i >= PRE) return;
    const float4 bi = g_boxes[n*PRE + i];
    const float ai = __fmul_rn(__fadd_rn(__fsub_rn(bi.z, bi.x), 1.0f),
                               __fadd_rn(__fsub_rn(bi.w, bi.y), 1.0f));
    unsigned long long bits = 0ull;
    const int jmax = min(64, PRE - cb*64);
    for (int c = 0; c < jmax; ++c) {
        int j = cb*64 + c;
        if (j <= i) continue;
        float4 bj = colbox[c];
        float aj = colarea[c];
        float xx1 = fmaxf(bi.x, bj.x), yy1 = fmaxf(bi.y, bj.y);
        float xx2 = fminf(bi.z, bj.z), yy2 = fminf(bi.w, bj.w);
        float iw = fmaxf(__fadd_rn(__fsub_rn(xx2, xx1), 1.0f), 0.0f);
        float ih = fmaxf(__fadd_rn(__fsub_rn(yy2, yy1), 1.0f), 0.0f);
        float inter = __fmul_rn(iw, ih);
        float denom = __fsub_rn(__fadd_rn(ai, aj), inter);
        float iou   = __fdiv_rn(inter, denom);
        if (iou > 0.5f) bits |= (1ull << c);
    }
    g_mask[((size_t)n*PRE + i)*MPITCH + cb] = bits;
}

// ---------------- Stage 4: lazy word-blocked scan -----------------------------
// One warp per batch. For word w: suppression = OR over all kept rows' word-w
// entry, gathered as ONE batch of independent L2 loads spread across lanes
// (lane l handles kept[l], kept[l+32], ...), then a 5-step shfl OR-reduce.
// Intra-word greedy resolved from the prefetched 64x64 diagonal smem block.
// Dependent chain: 47 load-batches, not 300 serial row loads.
extern "C" __global__ void __launch_bounds__(32)
scan_kernel(float* __restrict__ out) {
    const int n = blockIdx.x;
    const int lane = threadIdx.x;
    __shared__ unsigned long long s_diag[2][64];
    __shared__ int s_kept[POST];
    const unsigned FULL = 0xffffffffu;

    const unsigned long long* __restrict__ mbase =
        g_mask + (size_t)n * PRE * MPITCH;

    // preload diagonal block of word 0
    s_diag[0][lane]      = mbase[(size_t)lane * MPITCH];
    s_diag[0][32 + lane] = mbase[(size_t)(32 + lane) * MPITCH];
    __syncwarp();

    int nk = 0;
    for (int w = 0; w < NWORDS && nk < POST; ++w) {
        const int cb = w & 1, pb = cb ^ 1;

        // prefetch diagonal block of word w+1 (latency hidden under this word)
        if (w + 1 < NWORDS) {
            int base = (w + 1) * 64;
            int r0 = base + lane, r1 = base + 32 + lane;
            s_diag[pb][lane]      = (r0 < PRE)
                ? mbase[(size_t)r0 * MPITCH + (w + 1)] : 0ull;
            s_diag[pb][32 + lane] = (r1 < PRE)
                ? mbase[(size_t)r1 * MPITCH + (w + 1)] : 0ull;
        }

        // lazy suppression OR for word w: one parallel batch of loads
        unsigned long long acc = 0ull;
        for (int j = lane; j < nk; j += 32)
            acc |= mbase[(size_t)s_kept[j] * MPITCH + w];
#pragma unroll
        for (int off = 16; off; off >>= 1)
            acc |= __shfl_xor_sync(FULL, acc, off);

        unsigned long long cur =
            ((w == NWORDS - 1) ? ((1ull << 56) - 1ull) : ~0ull) & ~acc;

        // serial intra-word greedy resolve (uniform on all lanes; smem only)
        while (cur && nk < POST) {
            int b = __ffsll((long long)cur) - 1;
            s_kept[nk] = w * 64 + b;     // all lanes store identical value
            ++nk;
            cur &= ~(1ull << b);
            cur &= ~s_diag[cb][b];
        }
        __syncwarp();
    }
    __syncwarp();

    for (int r = lane; r < POST; r += 32) {
        float sc = 0.0f, x1 = 0.0f, y1 = 0.0f, x2 = 0.0f, y2 = 0.0f;
        if (r < nk) {
            int i = s_kept[r];
            float4 b = g_boxes[n*PRE + i];
            x1 = b.x; y1 = b.y; x2 = b.z; y2 = b.w;
            sc = g_topk_score[n*PRE + i];
        }
        float* o = out + (size_t)(n*POST + r)*5;
        o[1] = x1; o[2] = y1; o[3] = x2; o[4] = y2;
        g_selscore[n*POST + r] = sc;
    }
}

// ---------------- Stage 5: score column = batch 7's selected scores ---------
extern "C" __global__ void final_kernel(float* __restrict__ out) {
    int g = blockIdx.x*blockDim.x + threadIdx.x;
    if (g >= N_BATCH*POST) return;
    int r = g % POST;
    out[(size_t)g*5] = g_selscore[7*POST + r];
}

// ---------------- launch -----------------------------------------------------
extern "C" void kernel_launch(void* const* d_in, const int* in_sizes, int n_in,
                              void* d_out, int out_size) {
    const float* cls;
    const float* deltas;
    if (in_sizes[0] == N_BATCH*K_ANCH*HW) {     // 1,036,800
        cls = (const float*)d_in[0]; deltas = (const float*)d_in[1];
    } else {
        cls = (const float*)d_in[1]; deltas = (const float*)d_in[0];
    }
    float* out = (float*)d_out;

    cudaFuncSetAttribute(topk_kernel,
                         cudaFuncAttributeMaxDynamicSharedMemorySize, 65536);

    topk_kernel<<<N_BATCH, 1024, 65536>>>(cls);
    boxes_kernel<<<(N_BATCH*PRE + 255)/256, 256>>>(deltas);
    dim3 mg(NWORDS, NWORDS, N_BATCH);
    mask_kernel<<<mg, 64>>>();
    scan_kernel<<<N_BATCH, 32>>>(out);
    final_kernel<<<(N_BATCH*POST + 255)/256, 256>>>(out);
}